// round 12
// baseline (speedup 1.0000x reference)
#include <cuda_runtime.h>
#include <cstdint>

// ---------------------------------------------------------------------------
// out = relu(x - x@P + z@P) with P = c c^T (rank-1, ||c|| = 1).
// u = P[k,:] (k = argmax of first 128 diag entries), pkk = P[k,k]:
//   alpha_b = ((z.u) - (x_b.u)) / pkk
//   out     = relu(x + alpha_b * u)
//
// Fused kernel, ROWS=2 per block, 512 threads, ~40 regs -> 3 blocks/SM:
//   - fine granularity: 1024 blocks over 148 SMs -> ~1% SM-level tail
//     (R8's 4-row groups quantized to 3-or-4 groups/SM, ~15% tail)
//   - x held in registers through dot -> reduce -> apply (read once)
//   - u read once per block (amortized 2x), z folded straight into a partial
//   - one batched 3-way fixed-order reduction (deterministic)
// ---------------------------------------------------------------------------

#define ROWS_PER_BLK 2

// Specialized: D == 4096 (n4 = 1024), thread owns cols t and t+512.
__global__ void __launch_bounds__(512, 3)
pcav_fused2_kernel(const float* __restrict__ x, const float* __restrict__ P,
                   const float* __restrict__ z, float* __restrict__ out,
                   int D, int B) {
    __shared__ float s_red[16][3];
    __shared__ int   s_k;
    __shared__ float s_inv;
    __shared__ float s_alpha[ROWS_PER_BLK];

    const int t    = threadIdx.x;
    const int lane = t & 31;
    const int wid  = t >> 5;

    // ---- pivot: warp 0 only, first 128 diagonal entries ----
    if (wid == 0) {
        float best = -3.0e38f;
        int   bi   = 0;
        #pragma unroll
        for (int r = 0; r < 4; r++) {
            const int i = r * 32 + lane;
            float v = P[(size_t)i * D + i];
            if (v > best) { best = v; bi = i; }
        }
        #pragma unroll
        for (int o = 16; o > 0; o >>= 1) {
            float ov = __shfl_xor_sync(0xffffffffu, best, o);
            int   oi = __shfl_xor_sync(0xffffffffu, bi,   o);
            if (ov > best || (ov == best && oi < bi)) { best = ov; bi = oi; }
        }
        if (lane == 0) { s_k = bi; s_inv = 1.0f / best; }
    }
    __syncthreads();
    const int   k   = s_k;
    const float inv = s_inv;

    const int row0 = blockIdx.x * ROWS_PER_BLK;
    const int row1 = row0 + 1;
    const bool has1 = (row1 < B);

    const float4* __restrict__ u4 = reinterpret_cast<const float4*>(P + (size_t)k * D);
    const float4* __restrict__ z4 = reinterpret_cast<const float4*>(z);
    const float4* __restrict__ xr0 = reinterpret_cast<const float4*>(x + (size_t)row0 * D);
    const float4* __restrict__ xr1 = reinterpret_cast<const float4*>(x + (size_t)row1 * D);
    const int j0 = t, j1 = t + 512;

    // ---- front-batched x loads (deep MLP), kept in registers ----
    float4 a00 = xr0[j0];
    float4 a01 = xr0[j1];
    float4 a10, a11;
    if (has1) { a10 = xr1[j0]; a11 = xr1[j1]; }
    else      { a10 = make_float4(0.f, 0.f, 0.f, 0.f); a11 = a10; }

    // ---- u once per block; z folded immediately into its partial ----
    const float4 u0 = u4[j0], u1 = u4[j1];
    {
        // z loads issued after x/u — L2-hot 16KB, cheap
    }
    float4 zz0 = z4[j0], zz1 = z4[j1];

    float part[3];
    part[0] = ((fmaf(zz0.x, u0.x, zz0.y * u0.y) + fmaf(zz0.z, u0.z, zz0.w * u0.w)) +
               (fmaf(zz1.x, u1.x, zz1.y * u1.y) + fmaf(zz1.z, u1.z, zz1.w * u1.w)));
    part[1] = ((fmaf(a00.x, u0.x, a00.y * u0.y) + fmaf(a00.z, u0.z, a00.w * u0.w)) +
               (fmaf(a01.x, u1.x, a01.y * u1.y) + fmaf(a01.z, u1.z, a01.w * u1.w)));
    part[2] = ((fmaf(a10.x, u0.x, a10.y * u0.y) + fmaf(a10.z, u0.z, a10.w * u0.w)) +
               (fmaf(a11.x, u1.x, a11.y * u1.y) + fmaf(a11.z, u1.z, a11.w * u1.w)));

    // ---- batched fixed-order reduction (deterministic) ----
    #pragma unroll
    for (int i = 0; i < 3; i++) {
        float v = part[i];
        #pragma unroll
        for (int o = 16; o > 0; o >>= 1)
            v += __shfl_xor_sync(0xffffffffu, v, o);
        part[i] = v;
    }
    if (lane == 0) {
        s_red[wid][0] = part[0];
        s_red[wid][1] = part[1];
        s_red[wid][2] = part[2];
    }
    __syncthreads();
    if (wid == 0) {
        float v0 = (lane < 16) ? s_red[lane][0] : 0.0f;
        float v1 = (lane < 16) ? s_red[lane][1] : 0.0f;
        float v2 = (lane < 16) ? s_red[lane][2] : 0.0f;
        #pragma unroll
        for (int o = 8; o > 0; o >>= 1) {
            v0 += __shfl_xor_sync(0xffffffffu, v0, o);
            v1 += __shfl_xor_sync(0xffffffffu, v1, o);
            v2 += __shfl_xor_sync(0xffffffffu, v2, o);
        }
        if (lane == 0) {
            s_alpha[0] = (v0 - v1) * inv;
            s_alpha[1] = (v0 - v2) * inv;
        }
    }
    __syncthreads();

    // ---- apply + relu + store straight from registers ----
    {
        const float alpha = s_alpha[0];
        float4* __restrict__ orow = reinterpret_cast<float4*>(out + (size_t)row0 * D);
        float4 o0, o1;
        o0.x = fmaxf(fmaf(alpha, u0.x, a00.x), 0.0f);
        o0.y = fmaxf(fmaf(alpha, u0.y, a00.y), 0.0f);
        o0.z = fmaxf(fmaf(alpha, u0.z, a00.z), 0.0f);
        o0.w = fmaxf(fmaf(alpha, u0.w, a00.w), 0.0f);
        o1.x = fmaxf(fmaf(alpha, u1.x, a01.x), 0.0f);
        o1.y = fmaxf(fmaf(alpha, u1.y, a01.y), 0.0f);
        o1.z = fmaxf(fmaf(alpha, u1.z, a01.z), 0.0f);
        o1.w = fmaxf(fmaf(alpha, u1.w, a01.w), 0.0f);
        orow[j0] = o0;
        orow[j1] = o1;
    }
    if (has1) {
        const float alpha = s_alpha[1];
        float4* __restrict__ orow = reinterpret_cast<float4*>(out + (size_t)row1 * D);
        float4 o0, o1;
        o0.x = fmaxf(fmaf(alpha, u0.x, a10.x), 0.0f);
        o0.y = fmaxf(fmaf(alpha, u0.y, a10.y), 0.0f);
        o0.z = fmaxf(fmaf(alpha, u0.z, a10.z), 0.0f);
        o0.w = fmaxf(fmaf(alpha, u0.w, a10.w), 0.0f);
        o1.x = fmaxf(fmaf(alpha, u1.x, a11.x), 0.0f);
        o1.y = fmaxf(fmaf(alpha, u1.y, a11.y), 0.0f);
        o1.z = fmaxf(fmaf(alpha, u1.z, a11.z), 0.0f);
        o1.w = fmaxf(fmaf(alpha, u1.w, a11.w), 0.0f);
        orow[j0] = o0;
        orow[j1] = o1;
    }
}

// ---- generic fallback (any D multiple of 4, any B): fused one-row ----
__global__ void __launch_bounds__(512, 4)
pcav_generic_kernel(const float* __restrict__ x, const float* __restrict__ P,
                    const float* __restrict__ z, float* __restrict__ out, int D) {
    __shared__ float s_part[16];
    __shared__ int   s_k;
    __shared__ float s_inv;
    __shared__ float s_alpha;

    const int t    = threadIdx.x;
    const int lane = t & 31;
    const int wid  = t >> 5;

    if (wid == 0) {
        float best = -3.0e38f;
        int   bi   = 0;
        #pragma unroll
        for (int r = 0; r < 4; r++) {
            const int i = r * 32 + lane;
            if (i < D) {
                float v = P[(size_t)i * D + i];
                if (v > best) { best = v; bi = i; }
            }
        }
        #pragma unroll
        for (int o = 16; o > 0; o >>= 1) {
            float ov = __shfl_xor_sync(0xffffffffu, best, o);
            int   oi = __shfl_xor_sync(0xffffffffu, bi,   o);
            if (ov > best || (ov == best && oi < bi)) { best = ov; bi = oi; }
        }
        if (lane == 0) { s_k = bi; s_inv = 1.0f / best; }
    }
    __syncthreads();
    const int   k   = s_k;
    const float inv = s_inv;

    const size_t row_off = (size_t)blockIdx.x * (size_t)D;
    const float4* __restrict__ xr = reinterpret_cast<const float4*>(x + row_off);
    const float4* __restrict__ u4 = reinterpret_cast<const float4*>(P + (size_t)k * D);
    const float4* __restrict__ z4 = reinterpret_cast<const float4*>(z);
    float4* __restrict__ orow     = reinterpret_cast<float4*>(out + row_off);
    const int n4 = D >> 2;

    float part = 0.0f;
    for (int j = t; j < n4; j += 512) {
        float4 a = xr[j], u = u4[j], zz = z4[j];
        part = fmaf(zz.x - a.x, u.x, part);
        part = fmaf(zz.y - a.y, u.y, part);
        part = fmaf(zz.z - a.z, u.z, part);
        part = fmaf(zz.w - a.w, u.w, part);
    }
    #pragma unroll
    for (int o = 16; o > 0; o >>= 1)
        part += __shfl_xor_sync(0xffffffffu, part, o);
    if (lane == 0) s_part[wid] = part;
    __syncthreads();
    if (wid == 0) {
        float v = (lane < 16) ? s_part[lane] : 0.0f;
        #pragma unroll
        for (int o = 8; o > 0; o >>= 1)
            v += __shfl_xor_sync(0xffffffffu, v, o);
        if (lane == 0) s_alpha = v * inv;
    }
    __syncthreads();
    const float alpha = s_alpha;

    for (int j = t; j < n4; j += 512) {
        float4 a = xr[j], u = u4[j], o;
        o.x = fmaxf(fmaf(alpha, u.x, a.x), 0.0f);
        o.y = fmaxf(fmaf(alpha, u.y, a.y), 0.0f);
        o.z = fmaxf(fmaf(alpha, u.z, a.z), 0.0f);
        o.w = fmaxf(fmaf(alpha, u.w, a.w), 0.0f);
        orow[j] = o;
    }
}

extern "C" void kernel_launch(void* const* d_in, const int* in_sizes, int n_in,
                              void* d_out, int out_size) {
    // Identify inputs by element count: z = smallest (D), projection = D*D, x = B*D
    int zi = 0;
    for (int i = 1; i < n_in; i++)
        if (in_sizes[i] < in_sizes[zi]) zi = i;
    const int D = in_sizes[zi];

    int pi = -1, xi = -1;
    for (int i = 0; i < n_in; i++) {
        if (i == zi) continue;
        if ((long long)in_sizes[i] == (long long)D * (long long)D && pi < 0) pi = i;
        else xi = i;
    }
    if (pi < 0 || xi < 0) { xi = 0; pi = 1; }

    const float* x = (const float*)d_in[xi];
    const float* P = (const float*)d_in[pi];
    const float* z = (const float*)d_in[zi];
    float* out = (float*)d_out;

    const int B = in_sizes[xi] / D;

    if (D == 4096) {
        const int nblk = (B + ROWS_PER_BLK - 1) / ROWS_PER_BLK;
        pcav_fused2_kernel<<<nblk, 512>>>(x, P, z, out, D, B);
    } else {
        pcav_generic_kernel<<<B, 512>>>(x, P, z, out, D);
    }
}

// round 13
// speedup vs baseline: 1.0779x; 1.0779x over previous
#include <cuda_runtime.h>
#include <cstdint>

// ---------------------------------------------------------------------------
// out = relu(x - x@P + z@P) with P = c c^T (rank-1, ||c|| = 1).
// u = P[k,:] (k = argmax of first 128 diag entries), pkk = P[k,k]:
//   alpha_b = ((z.u) - (x_b.u)) / pkk
//   out     = relu(x + alpha_b * u)
//
// Fused kernel, ROWS=2 per block, 512 threads, ~40 regs -> 3 blocks/SM:
//   - fine granularity: 1024 blocks over 148 SMs -> ~1% SM-level tail
//     (R8's 4-row groups quantized to 3-or-4 groups/SM, ~15% tail)
//   - x held in registers through dot -> reduce -> apply (read once)
//   - u read once per block (amortized 2x), z folded straight into a partial
//   - one batched 3-way fixed-order reduction (deterministic)
// ---------------------------------------------------------------------------

#define ROWS_PER_BLK 2

// Specialized: D == 4096 (n4 = 1024), thread owns cols t and t+512.
__global__ void __launch_bounds__(512, 3)
pcav_fused2_kernel(const float* __restrict__ x, const float* __restrict__ P,
                   const float* __restrict__ z, float* __restrict__ out,
                   int D, int B) {
    __shared__ float s_red[16][3];
    __shared__ int   s_k;
    __shared__ float s_inv;
    __shared__ float s_alpha[ROWS_PER_BLK];

    const int t    = threadIdx.x;
    const int lane = t & 31;
    const int wid  = t >> 5;

    // ---- pivot: warp 0 only, first 128 diagonal entries ----
    if (wid == 0) {
        float best = -3.0e38f;
        int   bi   = 0;
        #pragma unroll
        for (int r = 0; r < 4; r++) {
            const int i = r * 32 + lane;
            float v = P[(size_t)i * D + i];
            if (v > best) { best = v; bi = i; }
        }
        #pragma unroll
        for (int o = 16; o > 0; o >>= 1) {
            float ov = __shfl_xor_sync(0xffffffffu, best, o);
            int   oi = __shfl_xor_sync(0xffffffffu, bi,   o);
            if (ov > best || (ov == best && oi < bi)) { best = ov; bi = oi; }
        }
        if (lane == 0) { s_k = bi; s_inv = 1.0f / best; }
    }
    __syncthreads();
    const int   k   = s_k;
    const float inv = s_inv;

    const int row0 = blockIdx.x * ROWS_PER_BLK;
    const int row1 = row0 + 1;
    const bool has1 = (row1 < B);

    const float4* __restrict__ u4 = reinterpret_cast<const float4*>(P + (size_t)k * D);
    const float4* __restrict__ z4 = reinterpret_cast<const float4*>(z);
    const float4* __restrict__ xr0 = reinterpret_cast<const float4*>(x + (size_t)row0 * D);
    const float4* __restrict__ xr1 = reinterpret_cast<const float4*>(x + (size_t)row1 * D);
    const int j0 = t, j1 = t + 512;

    // ---- front-batched x loads (deep MLP), kept in registers ----
    float4 a00 = xr0[j0];
    float4 a01 = xr0[j1];
    float4 a10, a11;
    if (has1) { a10 = xr1[j0]; a11 = xr1[j1]; }
    else      { a10 = make_float4(0.f, 0.f, 0.f, 0.f); a11 = a10; }

    // ---- u once per block; z folded immediately into its partial ----
    const float4 u0 = u4[j0], u1 = u4[j1];
    {
        // z loads issued after x/u — L2-hot 16KB, cheap
    }
    float4 zz0 = z4[j0], zz1 = z4[j1];

    float part[3];
    part[0] = ((fmaf(zz0.x, u0.x, zz0.y * u0.y) + fmaf(zz0.z, u0.z, zz0.w * u0.w)) +
               (fmaf(zz1.x, u1.x, zz1.y * u1.y) + fmaf(zz1.z, u1.z, zz1.w * u1.w)));
    part[1] = ((fmaf(a00.x, u0.x, a00.y * u0.y) + fmaf(a00.z, u0.z, a00.w * u0.w)) +
               (fmaf(a01.x, u1.x, a01.y * u1.y) + fmaf(a01.z, u1.z, a01.w * u1.w)));
    part[2] = ((fmaf(a10.x, u0.x, a10.y * u0.y) + fmaf(a10.z, u0.z, a10.w * u0.w)) +
               (fmaf(a11.x, u1.x, a11.y * u1.y) + fmaf(a11.z, u1.z, a11.w * u1.w)));

    // ---- batched fixed-order reduction (deterministic) ----
    #pragma unroll
    for (int i = 0; i < 3; i++) {
        float v = part[i];
        #pragma unroll
        for (int o = 16; o > 0; o >>= 1)
            v += __shfl_xor_sync(0xffffffffu, v, o);
        part[i] = v;
    }
    if (lane == 0) {
        s_red[wid][0] = part[0];
        s_red[wid][1] = part[1];
        s_red[wid][2] = part[2];
    }
    __syncthreads();
    if (wid == 0) {
        float v0 = (lane < 16) ? s_red[lane][0] : 0.0f;
        float v1 = (lane < 16) ? s_red[lane][1] : 0.0f;
        float v2 = (lane < 16) ? s_red[lane][2] : 0.0f;
        #pragma unroll
        for (int o = 8; o > 0; o >>= 1) {
            v0 += __shfl_xor_sync(0xffffffffu, v0, o);
            v1 += __shfl_xor_sync(0xffffffffu, v1, o);
            v2 += __shfl_xor_sync(0xffffffffu, v2, o);
        }
        if (lane == 0) {
            s_alpha[0] = (v0 - v1) * inv;
            s_alpha[1] = (v0 - v2) * inv;
        }
    }
    __syncthreads();

    // ---- apply + relu + store straight from registers ----
    {
        const float alpha = s_alpha[0];
        float4* __restrict__ orow = reinterpret_cast<float4*>(out + (size_t)row0 * D);
        float4 o0, o1;
        o0.x = fmaxf(fmaf(alpha, u0.x, a00.x), 0.0f);
        o0.y = fmaxf(fmaf(alpha, u0.y, a00.y), 0.0f);
        o0.z = fmaxf(fmaf(alpha, u0.z, a00.z), 0.0f);
        o0.w = fmaxf(fmaf(alpha, u0.w, a00.w), 0.0f);
        o1.x = fmaxf(fmaf(alpha, u1.x, a01.x), 0.0f);
        o1.y = fmaxf(fmaf(alpha, u1.y, a01.y), 0.0f);
        o1.z = fmaxf(fmaf(alpha, u1.z, a01.z), 0.0f);
        o1.w = fmaxf(fmaf(alpha, u1.w, a01.w), 0.0f);
        orow[j0] = o0;
        orow[j1] = o1;
    }
    if (has1) {
        const float alpha = s_alpha[1];
        float4* __restrict__ orow = reinterpret_cast<float4*>(out + (size_t)row1 * D);
        float4 o0, o1;
        o0.x = fmaxf(fmaf(alpha, u0.x, a10.x), 0.0f);
        o0.y = fmaxf(fmaf(alpha, u0.y, a10.y), 0.0f);
        o0.z = fmaxf(fmaf(alpha, u0.z, a10.z), 0.0f);
        o0.w = fmaxf(fmaf(alpha, u0.w, a10.w), 0.0f);
        o1.x = fmaxf(fmaf(alpha, u1.x, a11.x), 0.0f);
        o1.y = fmaxf(fmaf(alpha, u1.y, a11.y), 0.0f);
        o1.z = fmaxf(fmaf(alpha, u1.z, a11.z), 0.0f);
        o1.w = fmaxf(fmaf(alpha, u1.w, a11.w), 0.0f);
        orow[j0] = o0;
        orow[j1] = o1;
    }
}

// ---- generic fallback (any D multiple of 4, any B): fused one-row ----
__global__ void __launch_bounds__(512, 4)
pcav_generic_kernel(const float* __restrict__ x, const float* __restrict__ P,
                    const float* __restrict__ z, float* __restrict__ out, int D) {
    __shared__ float s_part[16];
    __shared__ int   s_k;
    __shared__ float s_inv;
    __shared__ float s_alpha;

    const int t    = threadIdx.x;
    const int lane = t & 31;
    const int wid  = t >> 5;

    if (wid == 0) {
        float best = -3.0e38f;
        int   bi   = 0;
        #pragma unroll
        for (int r = 0; r < 4; r++) {
            const int i = r * 32 + lane;
            if (i < D) {
                float v = P[(size_t)i * D + i];
                if (v > best) { best = v; bi = i; }
            }
        }
        #pragma unroll
        for (int o = 16; o > 0; o >>= 1) {
            float ov = __shfl_xor_sync(0xffffffffu, best, o);
            int   oi = __shfl_xor_sync(0xffffffffu, bi,   o);
            if (ov > best || (ov == best && oi < bi)) { best = ov; bi = oi; }
        }
        if (lane == 0) { s_k = bi; s_inv = 1.0f / best; }
    }
    __syncthreads();
    const int   k   = s_k;
    const float inv = s_inv;

    const size_t row_off = (size_t)blockIdx.x * (size_t)D;
    const float4* __restrict__ xr = reinterpret_cast<const float4*>(x + row_off);
    const float4* __restrict__ u4 = reinterpret_cast<const float4*>(P + (size_t)k * D);
    const float4* __restrict__ z4 = reinterpret_cast<const float4*>(z);
    float4* __restrict__ orow     = reinterpret_cast<float4*>(out + row_off);
    const int n4 = D >> 2;

    float part = 0.0f;
    for (int j = t; j < n4; j += 512) {
        float4 a = xr[j], u = u4[j], zz = z4[j];
        part = fmaf(zz.x - a.x, u.x, part);
        part = fmaf(zz.y - a.y, u.y, part);
        part = fmaf(zz.z - a.z, u.z, part);
        part = fmaf(zz.w - a.w, u.w, part);
    }
    #pragma unroll
    for (int o = 16; o > 0; o >>= 1)
        part += __shfl_xor_sync(0xffffffffu, part, o);
    if (lane == 0) s_part[wid] = part;
    __syncthreads();
    if (wid == 0) {
        float v = (lane < 16) ? s_part[lane] : 0.0f;
        #pragma unroll
        for (int o = 8; o > 0; o >>= 1)
            v += __shfl_xor_sync(0xffffffffu, v, o);
        if (lane == 0) s_alpha = v * inv;
    }
    __syncthreads();
    const float alpha = s_alpha;

    for (int j = t; j < n4; j += 512) {
        float4 a = xr[j], u = u4[j], o;
        o.x = fmaxf(fmaf(alpha, u.x, a.x), 0.0f);
        o.y = fmaxf(fmaf(alpha, u.y, a.y), 0.0f);
        o.z = fmaxf(fmaf(alpha, u.z, a.z), 0.0f);
        o.w = fmaxf(fmaf(alpha, u.w, a.w), 0.0f);
        orow[j] = o;
    }
}

extern "C" void kernel_launch(void* const* d_in, const int* in_sizes, int n_in,
                              void* d_out, int out_size) {
    // Identify inputs by element count: z = smallest (D), projection = D*D, x = B*D
    int zi = 0;
    for (int i = 1; i < n_in; i++)
        if (in_sizes[i] < in_sizes[zi]) zi = i;
    const int D = in_sizes[zi];

    int pi = -1, xi = -1;
    for (int i = 0; i < n_in; i++) {
        if (i == zi) continue;
        if ((long long)in_sizes[i] == (long long)D * (long long)D && pi < 0) pi = i;
        else xi = i;
    }
    if (pi < 0 || xi < 0) { xi = 0; pi = 1; }

    const float* x = (const float*)d_in[xi];
    const float* P = (const float*)d_in[pi];
    const float* z = (const float*)d_in[zi];
    float* out = (float*)d_out;

    const int B = in_sizes[xi] / D;

    if (D == 4096) {
        const int nblk = (B + ROWS_PER_BLK - 1) / ROWS_PER_BLK;
        pcav_fused2_kernel<<<nblk, 512>>>(x, P, z, out, D, B);
    } else {
        pcav_generic_kernel<<<B, 512>>>(x, P, z, out, D);
    }
}